// round 5
// baseline (speedup 1.0000x reference)
#include <cuda_runtime.h>
#include <cuda_fp16.h>
#include <cstdint>
#include <math.h>

// ---- Problem constants ----
#define BDIM 2048
#define DDIM 1024
#define UDIM 1024
#define NB   8
#define KACT 9216
#define NCOMB 4096

// ---- Scratch (device globals; no allocation allowed) ----
__device__ __half g_xh[BDIM * 2048];               // [x | h_prev] fp16
__device__ __half g_act[(size_t)BDIM * KACT];      // [silu | bases] fp16
__device__ __half g_comb[(size_t)BDIM * NCOMB];    // [h | kan0..2] fp16
__device__ __half g_wl[(size_t)2048 * 4096];       // fused [Wk;Wr], cols gate-interleaved u*4+g
__device__ __half g_wk[(size_t)KACT * 3072];       // fused KAN weights
__device__ __half g_wc[(size_t)4096 * 1024];       // combine weights
__device__ float  g_biasp[4096];                   // lstm bias permuted u*4+g

// ---- PTX helpers ----
__device__ __forceinline__ uint32_t smem_u32(const void* p) {
    uint32_t a;
    asm("{ .reg .u64 t; cvta.to.shared.u64 t, %1; cvt.u32.u64 %0, t; }"
        : "=r"(a) : "l"(p));
    return a;
}
__device__ __forceinline__ void cp16(uint32_t s, const void* g) {
    asm volatile("cp.async.cg.shared.global [%0], [%1], 16;" :: "r"(s), "l"(g));
}
__device__ __forceinline__ void cp_commit() {
    asm volatile("cp.async.commit_group;" ::: "memory");
}
template<int N> __device__ __forceinline__ void cp_wait() {
    asm volatile("cp.async.wait_group %0;" :: "n"(N) : "memory");
}
__device__ __forceinline__ void ldmA(uint32_t* r, uint32_t a) {
    asm volatile("ldmatrix.sync.aligned.m8n8.x4.shared.b16 {%0,%1,%2,%3}, [%4];"
                 : "=r"(r[0]), "=r"(r[1]), "=r"(r[2]), "=r"(r[3]) : "r"(a));
}
__device__ __forceinline__ void ldmBT(uint32_t* r, uint32_t a) {
    asm volatile("ldmatrix.sync.aligned.m8n8.x4.trans.shared.b16 {%0,%1,%2,%3}, [%4];"
                 : "=r"(r[0]), "=r"(r[1]), "=r"(r[2]), "=r"(r[3]) : "r"(a));
}
__device__ __forceinline__ void mma16(float* c, const uint32_t* a, const uint32_t* b) {
    asm volatile(
        "mma.sync.aligned.m16n8k16.row.col.f32.f16.f16.f32 "
        "{%0,%1,%2,%3}, {%4,%5,%6,%7}, {%8,%9}, {%0,%1,%2,%3};"
        : "+f"(c[0]), "+f"(c[1]), "+f"(c[2]), "+f"(c[3])
        : "r"(a[0]), "r"(a[1]), "r"(a[2]), "r"(a[3]), "r"(b[0]), "r"(b[1]));
}
__device__ __forceinline__ float sigf(float v) { return 1.0f / (1.0f + expf(-v)); }

// =====================================================================
// FP16 mma.sync GEMM: 128x128 CTA tile, 128 threads (4 warps 2x2),
// warp tile 64x64, BK=64, 3-stage cp.async.
// COUT: 0 = fp32 C (+bias), 1 = fp16 C, 2 = fused LSTM gate epilogue.
// =====================================================================
#define BKH 64
#define HAB 16384              // A tile bytes
#define HSTG 32768
#define HSSTG 3

extern __shared__ char smem_h[];

__device__ __forceinline__ uint32_t offA(int r, int c) {
    return (uint32_t)(r * 128 + ((c ^ (r & 7)) << 4));
}
__device__ __forceinline__ uint32_t offB(int k, int c) {
    return (uint32_t)(k * 256 + ((c ^ (k & 7)) << 4));
}

template<int COUT>
__global__ __launch_bounds__(128, 2) void gemm_h(
    const __half* __restrict__ A, int lda,
    const __half* __restrict__ B, int ldb,
    const float* __restrict__ bias,
    void* __restrict__ Cv, int ldc, int colOff, int K,
    const float* __restrict__ c_prev,
    float* __restrict__ out_h, float* __restrict__ out_c,
    __half* __restrict__ comb)
{
    const int tid = threadIdx.x;
    const int lane = tid & 31;
    const int w = tid >> 5;
    const int rowBase = blockIdx.y * 128;
    const int colBase = blockIdx.x * 128;

    const uint32_t sb = smem_u32(smem_h);

    float acc[4][8][4];
#pragma unroll
    for (int i = 0; i < 4; i++)
#pragma unroll
        for (int j = 0; j < 8; j++)
#pragma unroll
            for (int q = 0; q < 4; q++) acc[i][j][q] = 0.0f;

    const int nk = K / BKH;

    auto load_stage = [&](int t, int s) {
        const int kBase = t * BKH;
        const uint32_t sA = sb + s * HSTG;
        const uint32_t sB = sA + HAB;
#pragma unroll
        for (int i = 0; i < 8; i++) {               // A: 1024 chunks / 128 thr
            int idx = i * 128 + tid;
            int r = idx >> 3, c = idx & 7;
            cp16(sA + offA(r, c), A + (size_t)(rowBase + r) * lda + kBase + c * 8);
        }
#pragma unroll
        for (int i = 0; i < 8; i++) {               // B: 1024 chunks / 128 thr
            int idx = i * 128 + tid;
            int r = idx >> 4, c = idx & 15;
            cp16(sB + offB(r, c), B + (size_t)(kBase + r) * ldb + colBase + c * 8);
        }
    };

#pragma unroll
    for (int s = 0; s < HSSTG - 1; s++) { load_stage(s, s); cp_commit(); }

    const int wm = (w >> 1) * 64;
    const int wn = (w & 1) * 64;
    const int gid = lane >> 2;
    const int tg  = lane & 3;
    const int aRow = lane & 15;
    const int aSel = lane >> 4;
    const int bRow = lane & 15;
    const int bSel = lane >> 4;

    for (int t = 0; t < nk; t++) {
        cp_wait<HSSTG - 2>();
        __syncthreads();
        const int tn = t + HSSTG - 1;
        if (tn < nk) load_stage(tn, tn % HSSTG);
        cp_commit();

        const uint32_t sA = sb + (t % HSSTG) * HSTG;
        const uint32_t sB = sA + HAB;

#pragma unroll
        for (int ks = 0; ks < 4; ks++) {
            uint32_t af[4][4], bf[8][2];
#pragma unroll
            for (int i = 0; i < 4; i++)
                ldmA(af[i], sA + offA(wm + i * 16 + aRow, 2 * ks + aSel));
#pragma unroll
            for (int j2 = 0; j2 < 4; j2++) {
                uint32_t r4[4];
                ldmBT(r4, sB + offB(ks * 16 + bRow, (w & 1) * 8 + j2 * 2 + bSel));
                bf[2 * j2][0] = r4[0]; bf[2 * j2][1] = r4[1];
                bf[2 * j2 + 1][0] = r4[2]; bf[2 * j2 + 1][1] = r4[3];
            }
#pragma unroll
            for (int i = 0; i < 4; i++)
#pragma unroll
                for (int j = 0; j < 8; j++)
                    mma16(acc[i][j], af[i], bf[j]);
        }
    }

    // ---- epilogue ----
#pragma unroll
    for (int i = 0; i < 4; i++) {
        const int r0 = rowBase + wm + i * 16 + gid;
#pragma unroll
        for (int j = 0; j < 8; j++) {
            const int cn = colBase + wn + j * 8 + 2 * tg;
            if (COUT == 2) {
                // gate-interleaved cols: cn -> (u = cn>>2, g = cn&3)
                // lane tg even holds (zi,zf); lane tg odd holds (zg,zo); same row.
                const int u = cn >> 2;
                const float b0 = bias[cn], b1 = bias[cn + 1];
#pragma unroll
                for (int rr = 0; rr < 2; rr++) {
                    const int r = r0 + rr * 8;
                    float z0 = acc[i][j][2 * rr + 0] + b0;
                    float z1 = acc[i][j][2 * rr + 1] + b1;
                    float oz0 = __shfl_xor_sync(0xffffffffu, z0, 1);
                    float oz1 = __shfl_xor_sync(0xffffffffu, z1, 1);
                    float zi, zf, zg, zo;
                    if ((tg & 1) == 0) { zi = z0; zf = z1; zg = oz0; zo = oz1; }
                    else               { zi = oz0; zf = oz1; zg = z0; zo = z1; }
                    float cc = sigf(zf) * c_prev[(size_t)r * UDIM + u]
                             + sigf(zi) * tanhf(zg);
                    float hh = sigf(zo) * tanhf(cc);
                    if ((tg & 1) == 0) {
                        out_h[(size_t)r * UDIM + u] = hh;
                        comb[(size_t)r * NCOMB + u] = __float2half(hh);
                    } else {
                        out_c[(size_t)r * UDIM + u] = cc;
                    }
                }
            } else {
                float v0 = acc[i][j][0], v1 = acc[i][j][1];
                float v2 = acc[i][j][2], v3 = acc[i][j][3];
                if (COUT == 0 && bias) {
                    v0 += bias[cn]; v1 += bias[cn + 1];
                    v2 += bias[cn]; v3 += bias[cn + 1];
                }
                if (COUT == 0) {
                    float* C = (float*)Cv;
                    float2 p0; p0.x = v0; p0.y = v1;
                    float2 p1; p1.x = v2; p1.y = v3;
                    *(float2*)(C + (size_t)r0 * ldc + colOff + cn) = p0;
                    *(float2*)(C + (size_t)(r0 + 8) * ldc + colOff + cn) = p1;
                } else {
                    __half* C = (__half*)Cv;
                    *(__half2*)(C + (size_t)r0 * ldc + colOff + cn) = __floats2half2_rn(v0, v1);
                    *(__half2*)(C + (size_t)(r0 + 8) * ldc + colOff + cn) = __floats2half2_rn(v2, v3);
                }
            }
        }
    }
}

// =====================================================================
// Weight conversion
// =====================================================================
// LSTM weights: fused K rows [Wk;Wr], columns permuted n' = u*4+g
__global__ void cvt_lstm(const float* __restrict__ wk, const float* __restrict__ wr,
                         __half* __restrict__ o)
{
    int t = blockIdx.x * 256 + threadIdx.x;       // one thread per (k,u)
    int k = t >> 10, u = t & 1023;
    if (k >= 2048) return;
    const float* src = (k < 1024) ? wk + (size_t)k * 4096
                                  : wr + (size_t)(k - 1024) * 4096;
    float v0 = src[u], v1 = src[1024 + u], v2 = src[2048 + u], v3 = src[3072 + u];
    __half* d = o + (size_t)k * 4096 + u * 4;
    *(__half2*)(d)     = __floats2half2_rn(v0, v1);
    *(__half2*)(d + 2) = __floats2half2_rn(v2, v3);
}

__global__ void cvt_bias(const float* __restrict__ b, float* __restrict__ o)
{
    int u = threadIdx.x + blockIdx.x * 256;
    if (u >= 1024) return;
    o[u * 4 + 0] = b[u];
    o[u * 4 + 1] = b[1024 + u];
    o[u * 4 + 2] = b[2048 + u];
    o[u * 4 + 3] = b[3072 + u];
}

__global__ void cvt_kan(const float* __restrict__ bw, const float* __restrict__ sw,
                        __half* __restrict__ o)
{
    int col = (blockIdx.x * 256 + threadIdx.x) * 4;
    int k = blockIdx.y;
    int l = col >> 10, u = col & 1023;
    const float* s = (k < 1024)
        ? bw + ((size_t)l * 1024 + k) * 1024 + u
        : sw + ((size_t)l * 8192 + (k - 1024)) * 1024 + u;
    float4 v = *(const float4*)s;
    __half* d = o + (size_t)k * 3072 + col;
    *(__half2*)(d)     = __floats2half2_rn(v.x, v.y);
    *(__half2*)(d + 2) = __floats2half2_rn(v.z, v.w);
}

__global__ void cvt_comb(const float* __restrict__ wc, __half* __restrict__ o)
{
    int i = blockIdx.x * 256 + threadIdx.x;
    long e = (long)i * 4;
    float4 v = *(const float4*)(wc + e);
    *(__half2*)(o + e)     = __floats2half2_rn(v.x, v.y);
    *(__half2*)(o + e + 2) = __floats2half2_rn(v.z, v.w);
}

// =====================================================================
// Elementwise producers
// =====================================================================
__global__ void concat_xh_kernel(const float* __restrict__ x,
                                 const float* __restrict__ h,
                                 __half* __restrict__ xh)
{
    int i = blockIdx.x * 256 + threadIdx.x;
    long e = (long)i * 8;
    int b = (int)(e >> 11), c = (int)(e & 2047);
    const float* src = (c < 1024) ? x + (size_t)b * 1024 + c
                                  : h + (size_t)b * 1024 + (c - 1024);
    float4 v0 = *(const float4*)src;
    float4 v1 = *(const float4*)(src + 4);
    __half2 o[4];
    o[0] = __floats2half2_rn(v0.x, v0.y);
    o[1] = __floats2half2_rn(v0.z, v0.w);
    o[2] = __floats2half2_rn(v1.x, v1.y);
    o[3] = __floats2half2_rn(v1.z, v1.w);
    *(uint4*)(xh + e) = *(uint4*)o;
}

__device__ __forceinline__ float knot(int j) {
    return (float)(-1.0 + (2.0 / 5.0) * (double)(j - 3));
}
__global__ void act_kernel(const float* __restrict__ x, __half* __restrict__ act)
{
    int i = blockIdx.x * blockDim.x + threadIdx.x;
    if (i >= BDIM * DDIM) return;
    int b = i / DDIM, d = i - b * DDIM;
    float xv = x[i];
    float s = xv / (1.0f + expf(-xv));

    float bb[11];
#pragma unroll
    for (int j = 0; j < 11; j++)
        bb[j] = (xv >= knot(j) && xv < knot(j + 1)) ? 1.0f : 0.0f;
#pragma unroll
    for (int p = 1; p <= 3; p++) {
#pragma unroll
        for (int j = 0; j <= 10 - p; j++) {
            float tj  = knot(j),     tjp  = knot(j + p);
            float tj1 = knot(j + 1), tjp1 = knot(j + p + 1);
            bb[j] = (xv - tj) / (tjp - tj) * bb[j]
                  + (tjp1 - xv) / (tjp1 - tj1) * bb[j + 1];
        }
    }
    __half* row = act + (size_t)b * KACT;
    row[d] = __float2half(s);
    __half2 o[4];
    o[0] = __floats2half2_rn(bb[0], bb[1]);
    o[1] = __floats2half2_rn(bb[2], bb[3]);
    o[2] = __floats2half2_rn(bb[4], bb[5]);
    o[3] = __floats2half2_rn(bb[6], bb[7]);
    *(uint4*)(row + DDIM + d * NB) = *(uint4*)o;
}

// =====================================================================
// Launch
// =====================================================================
extern "C" void kernel_launch(void* const* d_in, const int* in_sizes, int n_in,
                              void* d_out, int out_size)
{
    const float* x       = (const float*)d_in[0];
    const float* h_prev  = (const float*)d_in[1];
    const float* c_prev  = (const float*)d_in[2];
    const float* lstm_k  = (const float*)d_in[3];
    const float* lstm_rk = (const float*)d_in[4];
    const float* lstm_b  = (const float*)d_in[5];
    const float* kan_bw  = (const float*)d_in[6];
    const float* kan_sw  = (const float*)d_in[7];
    const float* comb_w  = (const float*)d_in[8];
    const float* comb_b  = (const float*)d_in[9];

    float* out   = (float*)d_out;
    float* out_h = out + (size_t)BDIM * UDIM;
    float* out_c = out + (size_t)2 * BDIM * UDIM;

    __half *xh, *act, *comb, *wl, *wk, *wc;
    float* biasp;
    cudaGetSymbolAddress((void**)&xh,    g_xh);
    cudaGetSymbolAddress((void**)&act,   g_act);
    cudaGetSymbolAddress((void**)&comb,  g_comb);
    cudaGetSymbolAddress((void**)&wl,    g_wl);
    cudaGetSymbolAddress((void**)&wk,    g_wk);
    cudaGetSymbolAddress((void**)&wc,    g_wc);
    cudaGetSymbolAddress((void**)&biasp, g_biasp);

    const int DYN = HSSTG * HSTG;   // 98304
    cudaFuncSetAttribute(gemm_h<0>, cudaFuncAttributeMaxDynamicSharedMemorySize, DYN);
    cudaFuncSetAttribute(gemm_h<1>, cudaFuncAttributeMaxDynamicSharedMemorySize, DYN);
    cudaFuncSetAttribute(gemm_h<2>, cudaFuncAttributeMaxDynamicSharedMemorySize, DYN);

    // Weight conversion / fusion
    cvt_lstm<<<2048 * 1024 / 256, 256>>>(lstm_k, lstm_rk, wl);
    cvt_bias<<<4, 256>>>(lstm_b, biasp);
    cvt_kan<<<dim3(3, KACT), 256>>>(kan_bw, kan_sw, wk);
    cvt_comb<<<4096 * 1024 / 4 / 256, 256>>>(comb_w, wc);

    // Activation producers
    concat_xh_kernel<<<BDIM * 2048 / 8 / 256, 256>>>(x, h_prev, xh);
    act_kernel<<<(BDIM * DDIM + 255) / 256, 256>>>(x, act);

    // LSTM GEMM + fused gates: writes out_h, out_c, comb[:,0:1024]
    gemm_h<2><<<dim3(4096 / 128, BDIM / 128), 128, DYN>>>(
        xh, 2048, wl, 4096, biasp, nullptr, 0, 0, 2048,
        c_prev, out_h, out_c, comb);

    // KAN (3 layers fused, N=3072) -> comb[:, 1024+n] (fp16 out)
    gemm_h<1><<<dim3(3072 / 128, BDIM / 128), 128, DYN>>>(
        act, KACT, wk, 3072, nullptr, comb, NCOMB, 1024, KACT,
        nullptr, nullptr, nullptr, nullptr);

    // Combine: out = comb @ Wc + b (fp32 out)
    gemm_h<0><<<dim3(1024 / 128, BDIM / 128), 128, DYN>>>(
        comb, NCOMB, wc, 1024, comb_b, out, 1024, 0, 4096,
        nullptr, nullptr, nullptr, nullptr);
}

// round 6
// speedup vs baseline: 1.0191x; 1.0191x over previous
#include <cuda_runtime.h>
#include <cuda_fp16.h>
#include <cstdint>
#include <math.h>

// ---- Problem constants ----
#define BDIM 2048
#define DDIM 1024
#define UDIM 1024
#define NB   8
#define KACT 9216
#define NCOMB 4096

// ---- Scratch (device globals; no allocation allowed) ----
__device__ __half g_xh[BDIM * 2048];               // [x | h_prev] fp16
__device__ __half g_act[(size_t)BDIM * KACT];      // [silu | bases] fp16
__device__ __half g_comb[(size_t)BDIM * NCOMB];    // [h | kan0..2] fp16
__device__ __half g_wl[(size_t)2048 * 4096];       // fused [Wk;Wr], cols gate-interleaved u*4+g
__device__ __half g_wk[(size_t)KACT * 3072];       // fused KAN weights
__device__ __half g_wc[(size_t)4096 * 1024];       // combine weights
__device__ float  g_biasp[4096];                   // lstm bias permuted u*4+g

// ---- PTX helpers ----
__device__ __forceinline__ uint32_t smem_u32(const void* p) {
    uint32_t a;
    asm("{ .reg .u64 t; cvta.to.shared.u64 t, %1; cvt.u32.u64 %0, t; }"
        : "=r"(a) : "l"(p));
    return a;
}
__device__ __forceinline__ void cp16(uint32_t s, const void* g) {
    asm volatile("cp.async.cg.shared.global [%0], [%1], 16;" :: "r"(s), "l"(g));
}
__device__ __forceinline__ void cp_commit() {
    asm volatile("cp.async.commit_group;" ::: "memory");
}
template<int N> __device__ __forceinline__ void cp_wait() {
    asm volatile("cp.async.wait_group %0;" :: "n"(N) : "memory");
}
__device__ __forceinline__ void ldmA(uint32_t* r, uint32_t a) {
    asm volatile("ldmatrix.sync.aligned.m8n8.x4.shared.b16 {%0,%1,%2,%3}, [%4];"
                 : "=r"(r[0]), "=r"(r[1]), "=r"(r[2]), "=r"(r[3]) : "r"(a));
}
__device__ __forceinline__ void ldmBT(uint32_t* r, uint32_t a) {
    asm volatile("ldmatrix.sync.aligned.m8n8.x4.trans.shared.b16 {%0,%1,%2,%3}, [%4];"
                 : "=r"(r[0]), "=r"(r[1]), "=r"(r[2]), "=r"(r[3]) : "r"(a));
}
__device__ __forceinline__ void mma16(float* c, const uint32_t* a, const uint32_t* b) {
    asm volatile(
        "mma.sync.aligned.m16n8k16.row.col.f32.f16.f16.f32 "
        "{%0,%1,%2,%3}, {%4,%5,%6,%7}, {%8,%9}, {%0,%1,%2,%3};"
        : "+f"(c[0]), "+f"(c[1]), "+f"(c[2]), "+f"(c[3])
        : "r"(a[0]), "r"(a[1]), "r"(a[2]), "r"(a[3]), "r"(b[0]), "r"(b[1]));
}
__device__ __forceinline__ float sigf(float v) { return 1.0f / (1.0f + expf(-v)); }

// =====================================================================
// FP16 mma.sync GEMM: 128x128 CTA tile, 256 threads (8 warps 2x4),
// warp tile 64x32, BK=64, 3-stage cp.async.
// COUT: 0 = fp32 C (+bias), 1 = fp16 C, 2 = fused LSTM gate epilogue.
// =====================================================================
#define BKH 64
#define HAB 16384
#define HSTG 32768
#define HSSTG 3

extern __shared__ char smem_h[];

__device__ __forceinline__ uint32_t offA(int r, int c) {
    return (uint32_t)(r * 128 + ((c ^ (r & 7)) << 4));
}
__device__ __forceinline__ uint32_t offB(int k, int c) {
    return (uint32_t)(k * 256 + ((c ^ (k & 7)) << 4));
}

template<int COUT>
__global__ __launch_bounds__(256, 2) void gemm_h(
    const __half* __restrict__ A, int lda,
    const __half* __restrict__ B, int ldb,
    const float* __restrict__ bias,
    void* __restrict__ Cv, int ldc, int colOff, int K,
    const float* __restrict__ c_prev,
    float* __restrict__ out_h, float* __restrict__ out_c,
    __half* __restrict__ comb)
{
    const int tid = threadIdx.x;
    const int lane = tid & 31;
    const int w = tid >> 5;
    const int rowBase = blockIdx.y * 128;
    const int colBase = blockIdx.x * 128;

    const uint32_t sb = smem_u32(smem_h);

    float acc[4][4][4];
#pragma unroll
    for (int i = 0; i < 4; i++)
#pragma unroll
        for (int j = 0; j < 4; j++)
#pragma unroll
            for (int q = 0; q < 4; q++) acc[i][j][q] = 0.0f;

    const int nk = K / BKH;

    auto load_stage = [&](int t, int s) {
        const int kBase = t * BKH;
        const uint32_t sA = sb + s * HSTG;
        const uint32_t sB = sA + HAB;
#pragma unroll
        for (int i = 0; i < 4; i++) {
            int idx = i * 256 + tid;
            int r = idx >> 3, c = idx & 7;
            cp16(sA + offA(r, c), A + (size_t)(rowBase + r) * lda + kBase + c * 8);
        }
#pragma unroll
        for (int i = 0; i < 4; i++) {
            int idx = i * 256 + tid;
            int r = idx >> 4, c = idx & 15;
            cp16(sB + offB(r, c), B + (size_t)(kBase + r) * ldb + colBase + c * 8);
        }
    };

#pragma unroll
    for (int s = 0; s < HSSTG - 1; s++) { load_stage(s, s); cp_commit(); }

    const int wm = (w >> 2) * 64;
    const int wn = (w & 3) * 32;
    const int gid = lane >> 2;
    const int tg  = lane & 3;
    const int aRow = lane & 15;
    const int aSel = lane >> 4;
    const int bRow = lane & 15;
    const int bSel = lane >> 4;

    for (int t = 0; t < nk; t++) {
        cp_wait<HSSTG - 2>();
        __syncthreads();
        const int tn = t + HSSTG - 1;
        if (tn < nk) load_stage(tn, tn % HSSTG);
        cp_commit();

        const uint32_t sA = sb + (t % HSSTG) * HSTG;
        const uint32_t sB = sA + HAB;

#pragma unroll
        for (int ks = 0; ks < 4; ks++) {
            uint32_t af[4][4], bf[4][2];
#pragma unroll
            for (int i = 0; i < 4; i++)
                ldmA(af[i], sA + offA(wm + i * 16 + aRow, 2 * ks + aSel));
#pragma unroll
            for (int j2 = 0; j2 < 2; j2++) {
                uint32_t r4[4];
                ldmBT(r4, sB + offB(ks * 16 + bRow, (w & 3) * 4 + j2 * 2 + bSel));
                bf[2 * j2][0] = r4[0]; bf[2 * j2][1] = r4[1];
                bf[2 * j2 + 1][0] = r4[2]; bf[2 * j2 + 1][1] = r4[3];
            }
#pragma unroll
            for (int i = 0; i < 4; i++)
#pragma unroll
                for (int j = 0; j < 4; j++)
                    mma16(acc[i][j], af[i], bf[j]);
        }
    }

    // ---- epilogue ----
#pragma unroll
    for (int i = 0; i < 4; i++) {
        const int r0 = rowBase + wm + i * 16 + gid;
#pragma unroll
        for (int j = 0; j < 4; j++) {
            const int cn = colBase + wn + j * 8 + 2 * tg;
            if (COUT == 2) {
                // gate-interleaved cols: u = cn>>2. Lane tg parity even holds
                // (zi,zf), odd holds (zg,zo) of the SAME u; exchange via shfl_xor(1).
                const int u = cn >> 2;
                const float b0 = bias[cn], b1 = bias[cn + 1];
#pragma unroll
                for (int rr = 0; rr < 2; rr++) {
                    const int r = r0 + rr * 8;
                    float z0 = acc[i][j][2 * rr + 0] + b0;
                    float z1 = acc[i][j][2 * rr + 1] + b1;
                    float oz0 = __shfl_xor_sync(0xffffffffu, z0, 1);
                    float oz1 = __shfl_xor_sync(0xffffffffu, z1, 1);
                    float zi, zf, zg, zo;
                    if ((tg & 1) == 0) { zi = z0; zf = z1; zg = oz0; zo = oz1; }
                    else               { zi = oz0; zf = oz1; zg = z0; zo = z1; }
                    float cc = sigf(zf) * c_prev[(size_t)r * UDIM + u]
                             + sigf(zi) * tanhf(zg);
                    float hh = sigf(zo) * tanhf(cc);
                    if ((tg & 1) == 0) {
                        out_h[(size_t)r * UDIM + u] = hh;
                        comb[(size_t)r * NCOMB + u] = __float2half(hh);
                    } else {
                        out_c[(size_t)r * UDIM + u] = cc;
                    }
                }
            } else {
                float v0 = acc[i][j][0], v1 = acc[i][j][1];
                float v2 = acc[i][j][2], v3 = acc[i][j][3];
                if (COUT == 0 && bias) {
                    v0 += bias[cn]; v1 += bias[cn + 1];
                    v2 += bias[cn]; v3 += bias[cn + 1];
                }
                if (COUT == 0) {
                    float* C = (float*)Cv;
                    float2 p0; p0.x = v0; p0.y = v1;
                    float2 p1; p1.x = v2; p1.y = v3;
                    *(float2*)(C + (size_t)r0 * ldc + colOff + cn) = p0;
                    *(float2*)(C + (size_t)(r0 + 8) * ldc + colOff + cn) = p1;
                } else {
                    __half* C = (__half*)Cv;
                    *(__half2*)(C + (size_t)r0 * ldc + colOff + cn) = __floats2half2_rn(v0, v1);
                    *(__half2*)(C + (size_t)(r0 + 8) * ldc + colOff + cn) = __floats2half2_rn(v2, v3);
                }
            }
        }
    }
}

// =====================================================================
// Weight conversion
// =====================================================================
// LSTM weights: fused K rows [Wk;Wr], columns permuted n' = u*4+g
__global__ void cvt_lstm(const float* __restrict__ wk, const float* __restrict__ wr,
                         __half* __restrict__ o)
{
    int t = blockIdx.x * 256 + threadIdx.x;       // one thread per (k, u-pair)
    int k = t >> 9, up = (t & 511) * 2;
    if (k >= 2048) return;
    const float* src = (k < 1024) ? wk + (size_t)k * 4096
                                  : wr + (size_t)(k - 1024) * 4096;
    float2 a = *(const float2*)(src + up);
    float2 b = *(const float2*)(src + 1024 + up);
    float2 c = *(const float2*)(src + 2048 + up);
    float2 d = *(const float2*)(src + 3072 + up);
    __half2 h[4];
    h[0] = __floats2half2_rn(a.x, b.x);
    h[1] = __floats2half2_rn(c.x, d.x);
    h[2] = __floats2half2_rn(a.y, b.y);
    h[3] = __floats2half2_rn(c.y, d.y);
    *(uint4*)(o + (size_t)k * 4096 + up * 4) = *(uint4*)h;
}

__global__ void cvt_bias(const float* __restrict__ b, float* __restrict__ o)
{
    int u = threadIdx.x + blockIdx.x * 256;
    if (u >= 1024) return;
    o[u * 4 + 0] = b[u];
    o[u * 4 + 1] = b[1024 + u];
    o[u * 4 + 2] = b[2048 + u];
    o[u * 4 + 3] = b[3072 + u];
}

__global__ void cvt_kan(const float* __restrict__ bw, const float* __restrict__ sw,
                        __half* __restrict__ o)
{
    int col = (blockIdx.x * 128 + threadIdx.x) * 8;   // 0..3064, grid.x=3
    int k = blockIdx.y;
    int l = col >> 10, u = col & 1023;
    const float* s = (k < 1024)
        ? bw + ((size_t)l * 1024 + k) * 1024 + u
        : sw + ((size_t)l * 8192 + (k - 1024)) * 1024 + u;
    float4 v0 = *(const float4*)s;
    float4 v1 = *(const float4*)(s + 4);
    __half2 h[4];
    h[0] = __floats2half2_rn(v0.x, v0.y);
    h[1] = __floats2half2_rn(v0.z, v0.w);
    h[2] = __floats2half2_rn(v1.x, v1.y);
    h[3] = __floats2half2_rn(v1.z, v1.w);
    *(uint4*)(o + (size_t)k * 3072 + col) = *(uint4*)h;
}

__global__ void cvt_comb(const float* __restrict__ wc, __half* __restrict__ o)
{
    long e = ((long)blockIdx.x * 256 + threadIdx.x) * 8;
    float4 v0 = *(const float4*)(wc + e);
    float4 v1 = *(const float4*)(wc + e + 4);
    __half2 h[4];
    h[0] = __floats2half2_rn(v0.x, v0.y);
    h[1] = __floats2half2_rn(v0.z, v0.w);
    h[2] = __floats2half2_rn(v1.x, v1.y);
    h[3] = __floats2half2_rn(v1.z, v1.w);
    *(uint4*)(o + e) = *(uint4*)h;
}

// =====================================================================
// Elementwise producers
// =====================================================================
__global__ void concat_xh_kernel(const float* __restrict__ x,
                                 const float* __restrict__ h,
                                 __half* __restrict__ xh)
{
    int i = blockIdx.x * 256 + threadIdx.x;
    long e = (long)i * 8;
    int b = (int)(e >> 11), c = (int)(e & 2047);
    const float* src = (c < 1024) ? x + (size_t)b * 1024 + c
                                  : h + (size_t)b * 1024 + (c - 1024);
    float4 v0 = *(const float4*)src;
    float4 v1 = *(const float4*)(src + 4);
    __half2 o[4];
    o[0] = __floats2half2_rn(v0.x, v0.y);
    o[1] = __floats2half2_rn(v0.z, v0.w);
    o[2] = __floats2half2_rn(v1.x, v1.y);
    o[3] = __floats2half2_rn(v1.z, v1.w);
    *(uint4*)(xh + e) = *(uint4*)o;
}

__device__ __forceinline__ float knot(int j) {
    return (float)(-1.0 + (2.0 / 5.0) * (double)(j - 3));
}
__global__ void act_kernel(const float* __restrict__ x, __half* __restrict__ act)
{
    int i = blockIdx.x * blockDim.x + threadIdx.x;
    if (i >= BDIM * DDIM) return;
    int b = i / DDIM, d = i - b * DDIM;
    float xv = x[i];
    float s = xv / (1.0f + expf(-xv));

    float bb[11];
#pragma unroll
    for (int j = 0; j < 11; j++)
        bb[j] = (xv >= knot(j) && xv < knot(j + 1)) ? 1.0f : 0.0f;
#pragma unroll
    for (int p = 1; p <= 3; p++) {
#pragma unroll
        for (int j = 0; j <= 10 - p; j++) {
            float tj  = knot(j),     tjp  = knot(j + p);
            float tj1 = knot(j + 1), tjp1 = knot(j + p + 1);
            bb[j] = (xv - tj) / (tjp - tj) * bb[j]
                  + (tjp1 - xv) / (tjp1 - tj1) * bb[j + 1];
        }
    }
    __half* row = act + (size_t)b * KACT;
    row[d] = __float2half(s);
    __half2 o[4];
    o[0] = __floats2half2_rn(bb[0], bb[1]);
    o[1] = __floats2half2_rn(bb[2], bb[3]);
    o[2] = __floats2half2_rn(bb[4], bb[5]);
    o[3] = __floats2half2_rn(bb[6], bb[7]);
    *(uint4*)(row + DDIM + d * NB) = *(uint4*)o;
}

// =====================================================================
// Launch
// =====================================================================
extern "C" void kernel_launch(void* const* d_in, const int* in_sizes, int n_in,
                              void* d_out, int out_size)
{
    const float* x       = (const float*)d_in[0];
    const float* h_prev  = (const float*)d_in[1];
    const float* c_prev  = (const float*)d_in[2];
    const float* lstm_k  = (const float*)d_in[3];
    const float* lstm_rk = (const float*)d_in[4];
    const float* lstm_b  = (const float*)d_in[5];
    const float* kan_bw  = (const float*)d_in[6];
    const float* kan_sw  = (const float*)d_in[7];
    const float* comb_w  = (const float*)d_in[8];
    const float* comb_b  = (const float*)d_in[9];

    float* out   = (float*)d_out;
    float* out_h = out + (size_t)BDIM * UDIM;
    float* out_c = out + (size_t)2 * BDIM * UDIM;

    __half *xh, *act, *comb, *wl, *wk, *wc;
    float* biasp;
    cudaGetSymbolAddress((void**)&xh,    g_xh);
    cudaGetSymbolAddress((void**)&act,   g_act);
    cudaGetSymbolAddress((void**)&comb,  g_comb);
    cudaGetSymbolAddress((void**)&wl,    g_wl);
    cudaGetSymbolAddress((void**)&wk,    g_wk);
    cudaGetSymbolAddress((void**)&wc,    g_wc);
    cudaGetSymbolAddress((void**)&biasp, g_biasp);

    const int DYN = HSSTG * HSTG;   // 98304
    cudaFuncSetAttribute(gemm_h<0>, cudaFuncAttributeMaxDynamicSharedMemorySize, DYN);
    cudaFuncSetAttribute(gemm_h<1>, cudaFuncAttributeMaxDynamicSharedMemorySize, DYN);
    cudaFuncSetAttribute(gemm_h<2>, cudaFuncAttributeMaxDynamicSharedMemorySize, DYN);

    // Weight conversion / fusion
    cvt_lstm<<<2048 * 512 / 256, 256>>>(lstm_k, lstm_rk, wl);
    cvt_bias<<<4, 256>>>(lstm_b, biasp);
    cvt_kan<<<dim3(3, KACT), 128>>>(kan_bw, kan_sw, wk);
    cvt_comb<<<4096 * 1024 / 8 / 256, 256>>>(comb_w, wc);

    // Activation producers
    concat_xh_kernel<<<BDIM * 2048 / 8 / 256, 256>>>(x, h_prev, xh);
    act_kernel<<<(BDIM * DDIM + 255) / 256, 256>>>(x, act);

    // LSTM GEMM + fused gates: writes out_h, out_c, comb[:,0:1024]
    gemm_h<2><<<dim3(4096 / 128, BDIM / 128), 256, DYN>>>(
        xh, 2048, wl, 4096, biasp, nullptr, 0, 0, 2048,
        c_prev, out_h, out_c, comb);

    // KAN (3 layers fused, N=3072) -> comb[:, 1024+n] (fp16 out)
    gemm_h<1><<<dim3(3072 / 128, BDIM / 128), 256, DYN>>>(
        act, KACT, wk, 3072, nullptr, comb, NCOMB, 1024, KACT,
        nullptr, nullptr, nullptr, nullptr);

    // Combine: out = comb @ Wc + b (fp32 out)
    gemm_h<0><<<dim3(1024 / 128, BDIM / 128), 256, DYN>>>(
        comb, NCOMB, wc, 1024, comb_b, out, 1024, 0, 4096,
        nullptr, nullptr, nullptr, nullptr);
}